// round 2
// baseline (speedup 1.0000x reference)
#include <cuda_runtime.h>
#include <math.h>

// Problem constants
constexpr int B_   = 2;
constexpr int S_   = 2048;
constexpr int H_   = 4096;
constexpr int NH_  = 32;
constexpr int NKV_ = 8;
constexpr int HD_  = 128;
constexpr int BS_  = B_ * S_;        // 4096 rows
constexpr int QD_  = NH_ * HD_;      // 4096
constexpr int KD_  = NKV_ * HD_;     // 1024

// Scratch (device globals; no allocation allowed)
__device__ float g_q[(size_t)BS_ * QD_];     // 64 MB
__device__ float g_k[(size_t)BS_ * KD_];     // 16 MB
__device__ float g_v[(size_t)BS_ * KD_];     // 16 MB
__device__ float g_attn[(size_t)BS_ * QD_];  // 64 MB

// ---------------------------------------------------------------------------
// SGEMM: C[M,N] = A[M,K] @ B[K,N], all row-major fp32.
// 128x128 block tile, BK=16, 256 threads, 8x8 register tile per thread.
// ---------------------------------------------------------------------------
__global__ __launch_bounds__(256) void sgemm_kernel(
    const float* __restrict__ A, const float* __restrict__ Bw,
    float* __restrict__ C, int M, int N, int K) {
  constexpr int BK = 16;
  __shared__ float As[BK][128];   // A transposed: As[k][m]
  __shared__ float Bs[BK][128];   // Bs[k][n]

  const int tid = threadIdx.x;
  const int tx = tid & 15, ty = tid >> 4;
  const int m0 = blockIdx.y * 128, n0 = blockIdx.x * 128;

  // A tile load mapping: 128 rows x 16 cols, float4 along K
  const int arow = tid >> 2;              // 0..63 (plus +64)
  const int acol = (tid & 3) << 2;        // 0,4,8,12
  const float* Ap  = A + (size_t)(m0 + arow) * K + acol;
  const float* Ap2 = Ap + (size_t)64 * K;
  // B tile load mapping: 16 rows x 128 cols
  const int brow = tid >> 5;              // 0..7 (plus +8)
  const int bcol = (tid & 31) << 2;
  const float* Bp = Bw + (size_t)brow * N + n0 + bcol;

  float acc[8][8];
#pragma unroll
  for (int i = 0; i < 8; i++)
#pragma unroll
    for (int j = 0; j < 8; j++) acc[i][j] = 0.f;

  for (int k0 = 0; k0 < K; k0 += BK) {
    float4 a0 = *(const float4*)(Ap + k0);
    float4 a1 = *(const float4*)(Ap2 + k0);
    float4 b0 = *(const float4*)(Bp + (size_t)k0 * N);
    float4 b1 = *(const float4*)(Bp + (size_t)(k0 + 8) * N);
    __syncthreads();
    As[acol + 0][arow] = a0.x; As[acol + 1][arow] = a0.y;
    As[acol + 2][arow] = a0.z; As[acol + 3][arow] = a0.w;
    As[acol + 0][arow + 64] = a1.x; As[acol + 1][arow + 64] = a1.y;
    As[acol + 2][arow + 64] = a1.z; As[acol + 3][arow + 64] = a1.w;
    *(float4*)&Bs[brow][bcol]     = b0;
    *(float4*)&Bs[brow + 8][bcol] = b1;
    __syncthreads();
#pragma unroll
    for (int kk = 0; kk < BK; kk++) {
      float ra[8], rb[8];
      *(float4*)&ra[0] = *(const float4*)&As[kk][ty * 8];
      *(float4*)&ra[4] = *(const float4*)&As[kk][ty * 8 + 4];
      *(float4*)&rb[0] = *(const float4*)&Bs[kk][tx * 8];
      *(float4*)&rb[4] = *(const float4*)&Bs[kk][tx * 8 + 4];
#pragma unroll
      for (int i = 0; i < 8; i++)
#pragma unroll
        for (int j = 0; j < 8; j++)
          acc[i][j] = fmaf(ra[i], rb[j], acc[i][j]);
    }
  }
#pragma unroll
  for (int i = 0; i < 8; i++) {
    float* cp = C + (size_t)(m0 + ty * 8 + i) * N + n0 + tx * 8;
    *(float4*)cp       = make_float4(acc[i][0], acc[i][1], acc[i][2], acc[i][3]);
    *(float4*)(cp + 4) = make_float4(acc[i][4], acc[i][5], acc[i][6], acc[i][7]);
  }
}

// ---------------------------------------------------------------------------
// RoPE in place on q (32 heads) and k (8 heads).
// out[d]    = x[d]*cos[d]   - x[d+64]*sin[d]
// out[d+64] = x[d+64]*cos[d] + x[d]*sin[d]     (cos/sin periodic at 64)
// ---------------------------------------------------------------------------
__global__ void rope_kernel(float* __restrict__ q, float* __restrict__ k,
                            const float* __restrict__ cosb,
                            const float* __restrict__ sinb) {
  int gid = blockIdx.x * blockDim.x + threadIdx.x;
  // total = B*S*(NH+NKV)*64 = 10,485,760 (grid sized exactly)
  int d = gid & 63;
  int t = gid >> 6;
  int hh = t % (NH_ + NKV_);
  int bs = t / (NH_ + NKV_);
  float c  = cosb[bs * HD_ + d];
  float sn = sinb[bs * HD_ + d];
  float* p;
  if (hh < NH_) p = q + (size_t)bs * QD_ + hh * HD_ + d;
  else          p = k + (size_t)bs * KD_ + (hh - NH_) * HD_ + d;
  float x1 = p[0], x2 = p[64];
  p[0]  = fmaf(x1, c, -x2 * sn);
  p[64] = fmaf(x2, c,  x1 * sn);
}

// ---------------------------------------------------------------------------
// Causal flash attention, fp32. Block = (q-tile of 64) x head x batch.
// 256 threads as 16x16; score tile 4x4/thread, PV tile 4x8/thread.
// ---------------------------------------------------------------------------
constexpr int BQ = 64, BKT = 64;
constexpr int FLASH_SMEM_FLOATS =
    HD_ * BQ + HD_ * BKT + BKT * HD_ + BKT * BQ + BQ * 16;  // 29696
constexpr int FLASH_SMEM = FLASH_SMEM_FLOATS * 4;           // 118784 B

__global__ __launch_bounds__(256) void flash_kernel(
    const float* __restrict__ Q, const float* __restrict__ Kg,
    const float* __restrict__ Vg, float* __restrict__ Og) {
  extern __shared__ float sh[];
  float* Qs  = sh;                 // [128][64]  Q transposed (d-major)
  float* Ks  = sh + 8192;          // [128][64]  K transposed
  float* Vs  = sh + 16384;         // [64][128]  V natural
  float* Pt  = sh + 24576;         // [64][64]   P, kk-major
  float* red = sh + 28672;         // [64][16]   row reductions

  const int qt = blockIdx.x, h = blockIdx.y, b = blockIdx.z;
  const int kvh = h >> 2;          // n_rep = 4
  const int tid = threadIdx.x;
  const int tx = tid & 15, ty = tid >> 4;
  const int q0 = qt * BQ;
  const float scale = 0.08838834764831845f;  // 1/sqrt(128)

  // load Q tile, pre-scaled, transposed into smem
  for (int c = tid; c < BQ * HD_ / 4; c += 256) {
    int r = c >> 5;
    int d4 = (c & 31) << 2;
    float4 qv = *(const float4*)(Q + (size_t)(b * S_ + q0 + r) * QD_ + h * HD_ + d4);
    Qs[(d4 + 0) * BQ + r] = qv.x * scale;
    Qs[(d4 + 1) * BQ + r] = qv.y * scale;
    Qs[(d4 + 2) * BQ + r] = qv.z * scale;
    Qs[(d4 + 3) * BQ + r] = qv.w * scale;
  }

  float o[4][8];
#pragma unroll
  for (int i = 0; i < 4; i++)
#pragma unroll
    for (int j = 0; j < 8; j++) o[i][j] = 0.f;
  float m_i[4], l_i[4];
#pragma unroll
  for (int i = 0; i < 4; i++) { m_i[i] = -INFINITY; l_i[i] = 0.f; }

  for (int kt = 0; kt <= qt; kt++) {
    __syncthreads();  // protect smem reuse from previous iteration
    for (int c = tid; c < BKT * HD_ / 4; c += 256) {
      int r = c >> 5;
      int d4 = (c & 31) << 2;
      size_t gi = (size_t)(b * S_ + kt * BKT + r) * KD_ + kvh * HD_ + d4;
      float4 kv = *(const float4*)(Kg + gi);
      Ks[(d4 + 0) * BKT + r] = kv.x;
      Ks[(d4 + 1) * BKT + r] = kv.y;
      Ks[(d4 + 2) * BKT + r] = kv.z;
      Ks[(d4 + 3) * BKT + r] = kv.w;
      *(float4*)(Vs + r * HD_ + d4) = *(const float4*)(Vg + gi);
    }
    __syncthreads();

    // scores: S = (Q*scale) @ K^T, 4x4 per thread
    float s[4][4];
#pragma unroll
    for (int i = 0; i < 4; i++)
#pragma unroll
      for (int j = 0; j < 4; j++) s[i][j] = 0.f;
#pragma unroll 4
    for (int d = 0; d < HD_; d++) {
      float4 qv = *(const float4*)(Qs + d * BQ + ty * 4);
      float4 kv = *(const float4*)(Ks + d * BKT + tx * 4);
      float ra[4] = {qv.x, qv.y, qv.z, qv.w};
      float rb[4] = {kv.x, kv.y, kv.z, kv.w};
#pragma unroll
      for (int i = 0; i < 4; i++)
#pragma unroll
        for (int j = 0; j < 4; j++)
          s[i][j] = fmaf(ra[i], rb[j], s[i][j]);
    }
    if (kt == qt) {  // diagonal tile: causal mask (k0 == q0)
#pragma unroll
      for (int i = 0; i < 4; i++)
#pragma unroll
        for (int j = 0; j < 4; j++)
          if (tx * 4 + j > ty * 4 + i) s[i][j] = -1e30f;
    }

    // online softmax: row max across tx
#pragma unroll
    for (int i = 0; i < 4; i++) {
      float pm = fmaxf(fmaxf(s[i][0], s[i][1]), fmaxf(s[i][2], s[i][3]));
      red[(ty * 4 + i) * 16 + tx] = pm;
    }
    __syncthreads();
    float fac[4], mnew[4];
#pragma unroll
    for (int i = 0; i < 4; i++) {
      const float* rr = red + (ty * 4 + i) * 16;
      float rm = rr[0];
#pragma unroll
      for (int t = 1; t < 16; t++) rm = fmaxf(rm, rr[t]);
      mnew[i] = fmaxf(m_i[i], rm);
      fac[i]  = __expf(m_i[i] - mnew[i]);  // exp(-inf)=0 on first tile
      m_i[i]  = mnew[i];
    }
    float pr_[4][4], psum[4];
#pragma unroll
    for (int i = 0; i < 4; i++) {
      psum[i] = 0.f;
#pragma unroll
      for (int j = 0; j < 4; j++) {
        float e = __expf(s[i][j] - mnew[i]);
        pr_[i][j] = e;
        psum[i] += e;
      }
    }
    __syncthreads();  // red max-reads done before sum-writes
#pragma unroll
    for (int i = 0; i < 4; i++) {
      red[(ty * 4 + i) * 16 + tx] = psum[i];
#pragma unroll
      for (int j = 0; j < 4; j++)
        Pt[(tx * 4 + j) * BQ + ty * 4 + i] = pr_[i][j];
#pragma unroll
      for (int jj = 0; jj < 8; jj++) o[i][jj] *= fac[i];
    }
    __syncthreads();
#pragma unroll
    for (int i = 0; i < 4; i++) {
      const float* rr = red + (ty * 4 + i) * 16;
      float rs = 0.f;
#pragma unroll
      for (int t = 0; t < 16; t++) rs += rr[t];
      l_i[i] = l_i[i] * fac[i] + rs;
    }

    // O += P @ V, 4x8 per thread
#pragma unroll 2
    for (int kk = 0; kk < BKT; kk++) {
      float4 pv = *(const float4*)(Pt + kk * BQ + ty * 4);
      float4 v0 = *(const float4*)(Vs + kk * HD_ + tx * 8);
      float4 v1 = *(const float4*)(Vs + kk * HD_ + tx * 8 + 4);
      float rp[4] = {pv.x, pv.y, pv.z, pv.w};
      float rv[8] = {v0.x, v0.y, v0.z, v0.w, v1.x, v1.y, v1.z, v1.w};
#pragma unroll
      for (int i = 0; i < 4; i++)
#pragma unroll
        for (int jj = 0; jj < 8; jj++)
          o[i][jj] = fmaf(rp[i], rv[jj], o[i][jj]);
    }
  }

  // epilogue: normalize and store [b, s, h*HD + d]
#pragma unroll
  for (int i = 0; i < 4; i++) {
    float inv = 1.f / l_i[i];
    float* op = Og + (size_t)(b * S_ + q0 + ty * 4 + i) * QD_ + h * HD_ + tx * 8;
    *(float4*)op       = make_float4(o[i][0] * inv, o[i][1] * inv, o[i][2] * inv, o[i][3] * inv);
    *(float4*)(op + 4) = make_float4(o[i][4] * inv, o[i][5] * inv, o[i][6] * inv, o[i][7] * inv);
  }
}

// ---------------------------------------------------------------------------
extern "C" void kernel_launch(void* const* d_in, const int* in_sizes, int n_in,
                              void* d_out, int out_size) {
  const float* hs   = (const float*)d_in[0];
  const float* cosb = (const float*)d_in[1];
  const float* sinb = (const float*)d_in[2];
  const float* wq   = (const float*)d_in[3];
  const float* wk   = (const float*)d_in[4];
  const float* wv   = (const float*)d_in[5];
  const float* wo   = (const float*)d_in[6];
  float* out = (float*)d_out;

  float *qp, *kp, *vp, *ap;
  cudaGetSymbolAddress((void**)&qp, g_q);
  cudaGetSymbolAddress((void**)&kp, g_k);
  cudaGetSymbolAddress((void**)&vp, g_v);
  cudaGetSymbolAddress((void**)&ap, g_attn);

  // QKV projections
  sgemm_kernel<<<dim3(QD_ / 128, BS_ / 128), 256>>>(hs, wq, qp, BS_, QD_, H_);
  sgemm_kernel<<<dim3(KD_ / 128, BS_ / 128), 256>>>(hs, wk, kp, BS_, KD_, H_);
  sgemm_kernel<<<dim3(KD_ / 128, BS_ / 128), 256>>>(hs, wv, vp, BS_, KD_, H_);

  // RoPE on q and k (in place)
  {
    int total = B_ * S_ * (NH_ + NKV_) * 64;  // 10,485,760
    rope_kernel<<<total / 256, 256>>>(qp, kp, cosb, sinb);
  }

  // Causal GQA flash attention
  cudaFuncSetAttribute(flash_kernel, cudaFuncAttributeMaxDynamicSharedMemorySize,
                       FLASH_SMEM);
  flash_kernel<<<dim3(S_ / BQ, NH_, B_), 256, FLASH_SMEM>>>(qp, kp, vp, ap);

  // Output projection
  sgemm_kernel<<<dim3(H_ / 128, BS_ / 128), 256>>>(ap, wo, out, BS_, H_, H_);
}